// round 16
// baseline (speedup 1.0000x reference)
#include <cuda_runtime.h>
#include <cstdint>
#include <cstddef>

// ---- static problem sizes (match reference) ----
#define Bg 128
#define Nn 256
#define Dd 128
#define Kk 16
#define Mm 16
#define CG_ITERS 10
#define SINK_ITERS 50
#define CAP 128
#define STR 20           // smem stride in floats (80B, 16B-aligned)
#define STRC 321         // transposed Kr staging stride (odd -> conflict-light)
#define PROB (Bg * Kk)
#define NCTA 456         // persistent CTAs: 152 SMs x 3

#define FPAD(i) ((i) + 4 * ((i) >> 4))   // padded index: 16-blocks at stride 20

// ---- device scratch (no cudaMalloc anywhere) ----
__device__ float           g_C[(size_t)Bg * Nn * Nn];
__device__ float2          g_ell[(size_t)Bg * CAP * Nn];   // ELL packed (val, col): [b][e][row]
__device__ int             g_cnt[Bg * Nn];
__device__ float           g_cc1[Bg * Nn];
__device__ float           g_Mr[(size_t)PROB * Nn * Mm];   // Mcost (per-thread)
__device__ float           g_CT[(size_t)PROB * Nn * Mm];   // CTC (per-thread, incremental)
__device__ int             g_work;                         // dynamic work counter

// ============================ precompute ============================

__global__ void k_zero()
{
    if (blockIdx.x == 0 && threadIdx.x == 0) g_work = 0;   // reset every launch/replay
    size_t n = (size_t)Bg * Nn * Nn;
    for (size_t i = (size_t)blockIdx.x * blockDim.x + threadIdx.x; i < n;
         i += (size_t)gridDim.x * blockDim.x)
        g_C[i] = 0.f;
}

__global__ void k_scatter(const int* __restrict__ ei, int E)
{
    int e = blockIdx.x * blockDim.x + threadIdx.x;
    if (e >= E) return;
    int s = ei[e];
    int t = ei[E + e];
    int g = s >> 8;
    atomicAdd(&g_C[((size_t)(g * Nn + (s & 255))) * Nn + (t & 255)], 1.f);
}

// one warp per row: ballot-compaction into TRANSPOSED packed ELL [b][e][row]
__global__ void k_csr()
{
    int w = (blockIdx.x * blockDim.x + threadIdx.x) >> 5;
    int lane = threadIdx.x & 31;
    if (w >= Bg * Nn) return;
    int b = w >> 8, row = w & 255;
    const float* Crow = g_C + (size_t)w * Nn;
    float s2 = 0.f;
    int out = 0;
    size_t base = (size_t)b * CAP * Nn + row;
    for (int c0 = 0; c0 < Nn; c0 += 32) {
        float v = Crow[c0 + lane];
        s2 += v * v;
        unsigned m = __ballot_sync(0xffffffffu, v != 0.f);
        int off = __popc(m & ((1u << lane) - 1u));
        if (v != 0.f && (out + off) < CAP) {
            g_ell[base + (size_t)(out + off) * Nn] =
                make_float2(v, __int_as_float(c0 + lane));
        }
        out += __popc(m);
    }
    #pragma unroll
    for (int o = 16; o; o >>= 1) s2 += __shfl_xor_sync(0xffffffffu, s2, o);
    if (lane == 0) {
        g_cnt[w] = out > CAP ? CAP : out;
        g_cc1[w] = s2 * (1.f / Nn);
    }
}

// ============================ main kernel ============================

__device__ __forceinline__ float ex2(float x)
{
    float r; asm("ex2.approx.ftz.f32 %0, %1;" : "=f"(r) : "f"(x)); return r;
}
__device__ __forceinline__ float lg2(float x)
{
    float r; asm("lg2.approx.ftz.f32 %0, %1;" : "=f"(r) : "f"(x)); return r;
}
__device__ __forceinline__ float rcpa(float x)
{
    float r; asm("rcp.approx.ftz.f32 %0, %1;" : "=f"(r) : "f"(x)); return r;
}

__device__ __forceinline__ void ell_acc(const float* sBuf, float2 p, float R[16])
{
    int   c  = __float_as_int(p.y);
    float vv = p.x;
    const float4* tp = (const float4*)(sBuf + c * STR);
    float4 t0 = tp[0], t1 = tp[1], t2 = tp[2], t3 = tp[3];
    R[0]  += vv * t0.x; R[1]  += vv * t0.y; R[2]  += vv * t0.z; R[3]  += vv * t0.w;
    R[4]  += vv * t1.x; R[5]  += vv * t1.y; R[6]  += vv * t1.z; R[7]  += vv * t1.w;
    R[8]  += vv * t2.x; R[9]  += vv * t2.y; R[10] += vv * t2.z; R[11] += vv * t2.w;
    R[12] += vv * t3.x; R[13] += vv * t3.y; R[14] += vv * t3.z; R[15] += vv * t3.w;
}

// sparse row gather: unrolled x4 with front-batched loads (MLP >= 4)
__device__ __forceinline__ void spmm_row(const float* sBuf, size_t ebase, int cnt,
                                         int tid, float R[16])
{
    #pragma unroll
    for (int j = 0; j < 16; j++) R[j] = 0.f;
    size_t idx = ebase + tid;
    int e = 0;
    for (; e + 4 <= cnt; e += 4) {
        float2 p0 = g_ell[idx];
        float2 p1 = g_ell[idx + Nn];
        float2 p2 = g_ell[idx + 2 * Nn];
        float2 p3 = g_ell[idx + 3 * Nn];
        idx += 4 * Nn;
        ell_acc(sBuf, p0, R);
        ell_acc(sBuf, p1, R);
        ell_acc(sBuf, p2, R);
        ell_acc(sBuf, p3, R);
    }
    for (; e < cnt; e++) {
        float2 p = g_ell[idx];
        idx += Nn;
        ell_acc(sBuf, p, R);
    }
}

__global__ __launch_bounds__(256, 3)
void k_fgw(const float* __restrict__ x,
           const float* __restrict__ tA,
           const float* __restrict__ tF,
           const float* __restrict__ q0,
           const float* __restrict__ a0,
           float* __restrict__ out)
{
    // sT: features (2048) / T,dT staging (256*20=5120) / Kr transposed (16*321=5136)
    __shared__ __align__(16) float sT[5140];
    __shared__ __align__(16) float sU[Nn + Nn / 4];    // padded u buffer
    __shared__ __align__(16) float sW[Mm];             // scaled v (warm-started across CG)
    __shared__ __align__(16) float sPart[8 * Mm];      // line-search warp partials
    __shared__ __align__(16) float sC2[Mm * Mm];
    __shared__ int   sChgP[2];                         // parity convergence flags
    __shared__ int   sBid;                             // grabbed problem id
    __shared__ float scc2[Mm];
    __shared__ float sq256[Mm];                        // 256 * q_j
    __shared__ float sq[Mm];
    __shared__ float sFn[Mm];
    __shared__ float sred[16];
    __shared__ float sScal[4];

    const int tid  = threadIdx.x;
    const int lane = tid & 31;
    const int wid  = tid >> 5;
    const float L2E = 1.44269504088896340736f;

    const float alpha = 1.f / (1.f + expf(-a0[0]));

    const int rb   = lane & 15;               // col thread: owns rows [16rb, 16rb+16)
    const int jcol = 2 * wid + (lane >> 4);   // col thread: owned column

    for (;;) {
        // ===== grab next problem =====
        if (tid == 0) sBid = atomicAdd(&g_work, 1);
        __syncthreads();                       // broadcast bid + fence smem reuse
        const int bid = sBid;
        if (bid >= PROB) break;
        const int b = bid >> 4;
        const int k = bid & 15;
        const size_t sbase = ((size_t)bid * Nn + tid) * Mm;
        const size_t ebase = (size_t)b * CAP * Nn;

        // --- load C2, q softmax, features ---
        sC2[tid] = tA[k * 256 + tid];
        if (tid == 0) {
            float qv[16], mq = -1e30f;
            #pragma unroll
            for (int j = 0; j < 16; j++) { qv[j] = q0[k * 16 + j]; mq = fmaxf(mq, qv[j]); }
            float s = 0.f;
            #pragma unroll
            for (int j = 0; j < 16; j++) { qv[j] = ex2((qv[j] - mq) * L2E); s += qv[j]; }
            float inv = 1.f / s;
            #pragma unroll
            for (int j = 0; j < 16; j++) {
                float qq = qv[j] * inv;
                sq[j] = qq;
                sq256[j] = 256.f * qq;
            }
        }
        for (int t = tid; t < Mm * Dd; t += 256) sT[t] = tF[k * Mm * Dd + t];
        __syncthreads();

        if (tid < 16) {
            float s = 0.f;
            #pragma unroll
            for (int l = 0; l < 16; l++) { float c = sC2[tid * 16 + l]; s += c * c * sq[l]; }
            scc2[tid] = s;
            float fn = 0.f;
            for (int d = 0; d < Dd; d++) { float f = sT[tid * Dd + d]; fn += f * f; }
            sFn[tid] = fn;
            sW[tid] = 1.f;   // Sinkhorn scaling init per problem; warm across CG
        }

        // leader-lane persistent registers (per problem)
        float Wo = 1.f;
        float q256j = sq256[jcol];

        // --- Mcost row -> g_Mr ---
        {
            float Mr[16];
            #pragma unroll
            for (int j = 0; j < 16; j++) Mr[j] = 0.f;
            float xn = 0.f;
            const float4* xr = (const float4*)(x + ((size_t)(b * Nn + tid)) * Dd);
            for (int d4 = 0; d4 < Dd / 4; d4++) {
                float4 xv = xr[d4];
                xn += xv.x * xv.x + xv.y * xv.y + xv.z * xv.z + xv.w * xv.w;
                #pragma unroll
                for (int j = 0; j < 16; j++) {
                    float4 fv = ((const float4*)sT)[j * (Dd / 4) + d4];
                    Mr[j] += xv.x * fv.x + xv.y * fv.y + xv.z * fv.z + xv.w * fv.w;
                }
            }
            __syncthreads();   // sFn ready; feature reads done
            float4* mp = (float4*)(g_Mr + sbase);
            #pragma unroll
            for (int j4 = 0; j4 < 4; j4++) {
                float4 v;
                v.x = xn + sFn[j4 * 4 + 0] - 2.f * Mr[j4 * 4 + 0];
                v.y = xn + sFn[j4 * 4 + 1] - 2.f * Mr[j4 * 4 + 1];
                v.z = xn + sFn[j4 * 4 + 2] - 2.f * Mr[j4 * 4 + 2];
                v.w = xn + sFn[j4 * 4 + 3] - 2.f * Mr[j4 * 4 + 3];
                mp[j4] = v;
            }
        }

        const int grow = b * Nn + tid;
        const int cnt = g_cnt[grow];
        const float cc1 = g_cc1[grow];

        float T[16];
        #pragma unroll
        for (int j = 0; j < 16; j++) T[j] = sq[j] * (1.f / Nn);

        // ===== prologue: CTC0 = C1 @ T0 @ C2^T -> g_CT =====
        {
            float4* st = (float4*)(sT + tid * STR);
            st[0] = make_float4(T[0], T[1], T[2], T[3]);
            st[1] = make_float4(T[4], T[5], T[6], T[7]);
            st[2] = make_float4(T[8], T[9], T[10], T[11]);
            st[3] = make_float4(T[12], T[13], T[14], T[15]);
            __syncthreads();
            float R[16];
            spmm_row(sT, ebase, cnt, tid, R);
            float4* cp = (float4*)(g_CT + sbase);
            #pragma unroll
            for (int j4 = 0; j4 < 4; j4++) {
                float4 cv;
                float* c0 = (float*)&cv;
                #pragma unroll
                for (int jj = 0; jj < 4; jj++) {
                    float s = 0.f;
                    #pragma unroll
                    for (int l4 = 0; l4 < 4; l4++) {
                        float4 c4 = ((const float4*)sC2)[(j4 * 4 + jj) * 4 + l4];
                        s += R[l4 * 4 + 0] * c4.x + R[l4 * 4 + 1] * c4.y
                           + R[l4 * 4 + 2] * c4.z + R[l4 * 4 + 3] * c4.w;
                    }
                    c0[jj] = s;
                }
                cp[j4] = cv;
            }
            __syncthreads();   // spmm reads done before restage in B/C
        }

        for (int it = 0; it < CG_ITERS; it++) {
            // ===== B: gradient -> Kr, block max|grad| =====
            float Kr[16];
            float mxa = 0.f;
            {
                const float4* mp4 = (const float4*)(g_Mr + sbase);
                const float4* cp4 = (const float4*)(g_CT + sbase);
                #pragma unroll
                for (int j4 = 0; j4 < 4; j4++) {
                    float4 mv = mp4[j4];
                    float4 cv = cp4[j4];
                    float g0 = (1.f - alpha) * mv.x + 2.f * alpha * (cc1 + scc2[j4*4+0] - 2.f * cv.x);
                    float g1 = (1.f - alpha) * mv.y + 2.f * alpha * (cc1 + scc2[j4*4+1] - 2.f * cv.y);
                    float g2 = (1.f - alpha) * mv.z + 2.f * alpha * (cc1 + scc2[j4*4+2] - 2.f * cv.z);
                    float g3 = (1.f - alpha) * mv.w + 2.f * alpha * (cc1 + scc2[j4*4+3] - 2.f * cv.w);
                    Kr[j4*4+0] = g0; Kr[j4*4+1] = g1; Kr[j4*4+2] = g2; Kr[j4*4+3] = g3;
                    mxa = fmaxf(mxa, fmaxf(fmaxf(fabsf(g0), fabsf(g1)), fmaxf(fabsf(g2), fabsf(g3))));
                }
            }
            #pragma unroll
            for (int o = 16; o; o >>= 1) mxa = fmaxf(mxa, __shfl_xor_sync(0xffffffffu, mxa, o));
            if (lane == 0) sred[wid] = mxa;
            __syncthreads();
            {
                float m = fmaxf(fmaxf(fmaxf(sred[0], sred[1]), fmaxf(sred[2], sred[3])),
                                fmaxf(fmaxf(sred[4], sred[5]), fmaxf(sred[6], sred[7])));
                float cscale = -L2E / (0.01f * m + 1e-12f);
                float rmax = -1e30f;
                #pragma unroll
                for (int j = 0; j < 16; j++) { Kr[j] *= cscale; rmax = fmaxf(rmax, Kr[j]); }
                #pragma unroll
                for (int j = 0; j < 16; j++) Kr[j] = ex2(Kr[j] - rmax);   // (0,1]
            }
            __syncthreads();   // sred read done; sT free

            // ===== C: stage Kr transposed, read own column slice =====
            #pragma unroll
            for (int j = 0; j < 16; j++)
                sT[j * STRC + tid] = Kr[j];
            if (tid == 0) { sChgP[0] = 0; sChgP[1] = 0; }
            __syncthreads();
            float Kc_t[16];
            #pragma unroll
            for (int r = 0; r < 16; r++)
                Kc_t[r] = sT[jcol * STRC + 16 * rb + r];

            // ===== D: Sinkhorn, warm-started W, SOR, parity flags =====
            float U = 0.f;
            for (int sk = 0; sk < SINK_ITERS; sk++) {
                int p = sk & 1;
                {
                    const float4* wp = (const float4*)sW;
                    float4 w0 = wp[0], w1 = wp[1], w2 = wp[2], w3 = wp[3];
                    float s0 = Kr[0]  * w0.x + Kr[1]  * w0.y + Kr[2]  * w0.z + Kr[3]  * w0.w;
                    float s1 = Kr[4]  * w1.x + Kr[5]  * w1.y + Kr[6]  * w1.z + Kr[7]  * w1.w;
                    float s2 = Kr[8]  * w2.x + Kr[9]  * w2.y + Kr[10] * w2.z + Kr[11] * w2.w;
                    float s3 = Kr[12] * w3.x + Kr[13] * w3.y + Kr[14] * w3.z + Kr[15] * w3.w;
                    float s = fmaxf((s0 + s1) + (s2 + s3), 1e-30f);
                    U = rcpa(s);
                    sU[FPAD(tid)] = U;
                }
                __syncthreads();
                {
                    const float4* up = (const float4*)(sU + rb * STR);
                    float4 a = up[0], bb = up[1], c = up[2], d = up[3];
                    float part = Kc_t[0]  * a.x  + Kc_t[1]  * a.y  + Kc_t[2]  * a.z  + Kc_t[3]  * a.w
                               + Kc_t[4]  * bb.x + Kc_t[5]  * bb.y + Kc_t[6]  * bb.z + Kc_t[7]  * bb.w
                               + Kc_t[8]  * c.x  + Kc_t[9]  * c.y  + Kc_t[10] * c.z  + Kc_t[11] * c.w
                               + Kc_t[12] * d.x  + Kc_t[13] * d.y  + Kc_t[14] * d.z  + Kc_t[15] * d.w;
                    part += __shfl_xor_sync(0xffffffffu, part, 1);
                    part += __shfl_xor_sync(0xffffffffu, part, 2);
                    part += __shfl_xor_sync(0xffffffffu, part, 4);
                    part += __shfl_xor_sync(0xffffffffu, part, 8);
                    if (rb == 0) {
                        float Wn = q256j * rcpa(fmaxf(part, 1e-30f));
                        bool chg = fabsf(Wn - Wo) > 1e-4f * Wo;
                        float Wr = Wn;
                        if (chg && sk > 0)
                            Wr = Wn * ex2(0.4f * lg2(Wn * rcpa(Wo)));
                        sW[jcol] = Wr;
                        Wo = Wr;
                        if (chg) sChgP[p] = 1;
                    }
                    if (tid == 0) sChgP[p ^ 1] = 0;
                }
                __syncthreads();
                if (sChgP[p] == 0) break;
            }

            // ===== E: dT ; step-size early exit =====
            float dT[16];
            float mdt = 0.f, mT = 0.f;
            {
                const float4* wp = (const float4*)sW;
                float4 w0 = wp[0], w1 = wp[1], w2 = wp[2], w3 = wp[3];
                float Wv[16] = { w0.x,w0.y,w0.z,w0.w, w1.x,w1.y,w1.z,w1.w,
                                 w2.x,w2.y,w2.z,w2.w, w3.x,w3.y,w3.z,w3.w };
                float Us = U * (1.f / 256.f);
                #pragma unroll
                for (int j = 0; j < 16; j++) {
                    dT[j] = Us * Kr[j] * Wv[j] - T[j];
                    mdt = fmaxf(mdt, fabsf(dT[j]));
                    mT  = fmaxf(mT, T[j]);
                }
            }
            #pragma unroll
            for (int o = 16; o; o >>= 1) {
                mdt = fmaxf(mdt, __shfl_xor_sync(0xffffffffu, mdt, o));
                mT  = fmaxf(mT,  __shfl_xor_sync(0xffffffffu, mT,  o));
            }
            if (lane == 0) { sred[wid] = mdt; sred[8 + wid] = mT; }
            __syncthreads();
            {
                float Mdt = fmaxf(fmaxf(fmaxf(sred[0], sred[1]), fmaxf(sred[2], sred[3])),
                                  fmaxf(fmaxf(sred[4], sred[5]), fmaxf(sred[6], sred[7])));
                float MT  = fmaxf(fmaxf(fmaxf(sred[8], sred[9]), fmaxf(sred[10], sred[11])),
                                  fmaxf(fmaxf(sred[12], sred[13]), fmaxf(sred[14], sred[15])));
                if (Mdt <= 1e-5f * MT) break;
            }

            // ===== F: D = C1 @ dT @ C2^T =====
            {
                float4* st = (float4*)(sT + tid * STR);
                st[0] = make_float4(dT[0], dT[1], dT[2], dT[3]);
                st[1] = make_float4(dT[4], dT[5], dT[6], dT[7]);
                st[2] = make_float4(dT[8], dT[9], dT[10], dT[11]);
                st[3] = make_float4(dT[12], dT[13], dT[14], dT[15]);
            }
            __syncthreads();
            float Rd[16];
            spmm_row(sT, ebase, cnt, tid, Rd);
            float D[16];
            #pragma unroll
            for (int jj = 0; jj < 16; jj++) {
                float s = 0.f;
                #pragma unroll
                for (int l4 = 0; l4 < 4; l4++) {
                    float4 c4 = ((const float4*)sC2)[jj * 4 + l4];
                    s += Rd[l4 * 4 + 0] * c4.x + Rd[l4 * 4 + 1] * c4.y
                       + Rd[l4 * 4 + 2] * c4.z + Rd[l4 * 4 + 3] * c4.w;
                }
                D[jj] = s;
            }

            // ===== G: line search + incremental CTC update =====
            float pa = 0.f, pb1 = 0.f, pb2 = 0.f, pb3 = 0.f;
            {
                const float4* mp4 = (const float4*)(g_Mr + sbase);
                const float4* cp4 = (const float4*)(g_CT + sbase);
                #pragma unroll
                for (int j4 = 0; j4 < 4; j4++) {
                    float4 mv = mp4[j4];
                    float4 cv = cp4[j4];
                    pa  += D[j4*4+0] * dT[j4*4+0] + D[j4*4+1] * dT[j4*4+1]
                         + D[j4*4+2] * dT[j4*4+2] + D[j4*4+3] * dT[j4*4+3];
                    pb1 += mv.x * dT[j4*4+0] + mv.y * dT[j4*4+1]
                         + mv.z * dT[j4*4+2] + mv.w * dT[j4*4+3];
                    pb2 += D[j4*4+0] * T[j4*4+0] + D[j4*4+1] * T[j4*4+1]
                         + D[j4*4+2] * T[j4*4+2] + D[j4*4+3] * T[j4*4+3];
                    pb3 += cv.x * dT[j4*4+0] + cv.y * dT[j4*4+1]
                         + cv.z * dT[j4*4+2] + cv.w * dT[j4*4+3];
                }
            }
            #pragma unroll
            for (int o = 16; o; o >>= 1) {
                pa  += __shfl_xor_sync(0xffffffffu, pa, o);
                pb1 += __shfl_xor_sync(0xffffffffu, pb1, o);
                pb2 += __shfl_xor_sync(0xffffffffu, pb2, o);
                pb3 += __shfl_xor_sync(0xffffffffu, pb3, o);
            }
            if (lane == 0) {
                sPart[wid * 4 + 0] = pa;  sPart[wid * 4 + 1] = pb1;
                sPart[wid * 4 + 2] = pb2; sPart[wid * 4 + 3] = pb3;
            }
            __syncthreads();
            if (tid == 0) {
                float Sa = 0.f, S1 = 0.f, S2 = 0.f, S3 = 0.f;
                #pragma unroll
                for (int w = 0; w < 8; w++) {
                    Sa += sPart[w * 4 + 0]; S1 += sPart[w * 4 + 1];
                    S2 += sPart[w * 4 + 2]; S3 += sPart[w * 4 + 3];
                }
                float A  = -2.f * alpha * Sa;
                float Bc = (1.f - alpha) * S1 - 2.f * alpha * (S2 + S3);
                float tstep;
                if (A > 0.f) {
                    tstep = -Bc / (2.f * A + 1e-16f);
                    tstep = fminf(1.f, fmaxf(0.f, tstep));
                } else {
                    tstep = (A + Bc < 0.f) ? 1.f : 0.f;
                }
                sScal[1] = tstep;
            }
            __syncthreads();
            float ts = sScal[1];
            if (ts == 0.f) break;     // exact no-op for all remaining CG iterations
            #pragma unroll
            for (int j = 0; j < 16; j++) T[j] += ts * dT[j];
            {
                float4* cp = (float4*)(g_CT + sbase);
                #pragma unroll
                for (int j4 = 0; j4 < 4; j4++) {
                    float4 cv = cp[j4];
                    cv.x += ts * D[j4*4+0]; cv.y += ts * D[j4*4+1];
                    cv.z += ts * D[j4*4+2]; cv.w += ts * D[j4*4+3];
                    cp[j4] = cv;
                }
            }
        }

        // ===== epilogue (CTC from g_CT matches final T) =====
        float pg = 0.f, pl = 0.f;
        {
            const float4* mp4 = (const float4*)(g_Mr + sbase);
            const float4* cp4 = (const float4*)(g_CT + sbase);
            #pragma unroll
            for (int j4 = 0; j4 < 4; j4++) {
                float4 mv = mp4[j4];
                float4 cv = cp4[j4];
                pg += (cc1 + scc2[j4*4+0] - 2.f * cv.x) * T[j4*4+0]
                    + (cc1 + scc2[j4*4+1] - 2.f * cv.y) * T[j4*4+1]
                    + (cc1 + scc2[j4*4+2] - 2.f * cv.z) * T[j4*4+2]
                    + (cc1 + scc2[j4*4+3] - 2.f * cv.w) * T[j4*4+3];
                pl += mv.x * T[j4*4+0] + mv.y * T[j4*4+1]
                    + mv.z * T[j4*4+2] + mv.w * T[j4*4+3];
            }
        }
        #pragma unroll
        for (int o = 16; o; o >>= 1) {
            pg += __shfl_xor_sync(0xffffffffu, pg, o);
            pl += __shfl_xor_sync(0xffffffffu, pl, o);
        }
        if (lane == 0) { sPart[wid * 2] = pg; sPart[wid * 2 + 1] = pl; }
        __syncthreads();
        if (tid == 0) {
            float Gw = 0.f, L = 0.f;
            #pragma unroll
            for (int w = 0; w < 8; w++) { Gw += sPart[w * 2]; L += sPart[w * 2 + 1]; }
            out[bid] = (1.f - alpha) * L + alpha * Gw;
        }
        // next loop iteration starts with a barrier (bid broadcast) which also
        // fences all smem reuse across problems
    }
}

// ============================ launch ============================

extern "C" void kernel_launch(void* const* d_in, const int* in_sizes, int n_in,
                              void* d_out, int out_size)
{
    const float* x  = (const float*)d_in[0];
    const int*   ei = (const int*)  d_in[1];
    const float* tA = (const float*)d_in[3];
    const float* tF = (const float*)d_in[4];
    const float* q0 = (const float*)d_in[5];
    const float* a0 = (const float*)d_in[6];
    int E = in_sizes[1] / 2;

    k_zero<<<8192, 256>>>();
    k_scatter<<<(E + 255) / 256, 256>>>(ei, E);
    k_csr<<<(Bg * Nn * 32 + 255) / 256, 256>>>();
    k_fgw<<<NCTA, 256>>>(x, tA, tF, q0, a0, (float*)d_out);
}

// round 17
// speedup vs baseline: 1.1106x; 1.1106x over previous
#include <cuda_runtime.h>
#include <cstdint>
#include <cstddef>

// ---- static problem sizes (match reference) ----
#define Bg 128
#define Nn 256
#define Dd 128
#define Kk 16
#define Mm 16
#define CG_ITERS 10
#define SINK_ITERS 50
#define CAP 128
#define STR 20           // smem stride in floats (80B, 16B-aligned)
#define STRC 321         // transposed Kr staging stride (odd -> conflict-light)
#define PROB (Bg * Kk)
#define NCTA 456         // persistent CTAs: 152 SMs x 3

#define FPAD(i) ((i) + 4 * ((i) >> 4))   // padded index: 16-blocks at stride 20

// ---- device scratch (no cudaMalloc anywhere) ----
__device__ float           g_C[(size_t)Bg * Nn * Nn];
__device__ float2          g_ell[(size_t)Bg * CAP * Nn];   // ELL packed (val, col): [b][e][row]
__device__ int             g_cnt[Bg * Nn];
__device__ float           g_cc1[Bg * Nn];
__device__ float           g_rs[Bg * Nn];                  // (C1 @ p)_i = rowsum_i / 256
__device__ float           g_Mr[(size_t)PROB * Nn * Mm];   // Mcost (per-thread)
__device__ float           g_CT[(size_t)PROB * Nn * Mm];   // CTC (per-thread, incremental)
__device__ int             g_work;                         // dynamic work counter

// ============================ precompute ============================

__global__ void k_zero()
{
    if (blockIdx.x == 0 && threadIdx.x == 0) g_work = 0;   // reset every launch/replay
    size_t n = (size_t)Bg * Nn * Nn;
    for (size_t i = (size_t)blockIdx.x * blockDim.x + threadIdx.x; i < n;
         i += (size_t)gridDim.x * blockDim.x)
        g_C[i] = 0.f;
}

__global__ void k_scatter(const int* __restrict__ ei, int E)
{
    int e = blockIdx.x * blockDim.x + threadIdx.x;
    if (e >= E) return;
    int s = ei[e];
    int t = ei[E + e];
    int g = s >> 8;
    atomicAdd(&g_C[((size_t)(g * Nn + (s & 255))) * Nn + (t & 255)], 1.f);
}

// one warp per row: ballot-compaction into TRANSPOSED packed ELL [b][e][row]
__global__ void k_csr()
{
    int w = (blockIdx.x * blockDim.x + threadIdx.x) >> 5;
    int lane = threadIdx.x & 31;
    if (w >= Bg * Nn) return;
    int b = w >> 8, row = w & 255;
    const float* Crow = g_C + (size_t)w * Nn;
    float s2 = 0.f, s1 = 0.f;
    int out = 0;
    size_t base = (size_t)b * CAP * Nn + row;
    for (int c0 = 0; c0 < Nn; c0 += 32) {
        float v = Crow[c0 + lane];
        s2 += v * v;
        s1 += v;
        unsigned m = __ballot_sync(0xffffffffu, v != 0.f);
        int off = __popc(m & ((1u << lane) - 1u));
        if (v != 0.f && (out + off) < CAP) {
            g_ell[base + (size_t)(out + off) * Nn] =
                make_float2(v, __int_as_float(c0 + lane));
        }
        out += __popc(m);
    }
    #pragma unroll
    for (int o = 16; o; o >>= 1) {
        s2 += __shfl_xor_sync(0xffffffffu, s2, o);
        s1 += __shfl_xor_sync(0xffffffffu, s1, o);
    }
    if (lane == 0) {
        g_cnt[w] = out > CAP ? CAP : out;
        g_cc1[w] = s2 * (1.f / Nn);
        g_rs[w]  = s1 * (1.f / Nn);
    }
}

// ============================ main kernel ============================

__device__ __forceinline__ float ex2(float x)
{
    float r; asm("ex2.approx.ftz.f32 %0, %1;" : "=f"(r) : "f"(x)); return r;
}
__device__ __forceinline__ float lg2(float x)
{
    float r; asm("lg2.approx.ftz.f32 %0, %1;" : "=f"(r) : "f"(x)); return r;
}
__device__ __forceinline__ float rcpa(float x)
{
    float r; asm("rcp.approx.ftz.f32 %0, %1;" : "=f"(r) : "f"(x)); return r;
}

__device__ __forceinline__ void ell_acc(const float* sBuf, float2 p, float R[16])
{
    int   c  = __float_as_int(p.y);
    float vv = p.x;
    const float4* tp = (const float4*)(sBuf + c * STR);
    float4 t0 = tp[0], t1 = tp[1], t2 = tp[2], t3 = tp[3];
    R[0]  += vv * t0.x; R[1]  += vv * t0.y; R[2]  += vv * t0.z; R[3]  += vv * t0.w;
    R[4]  += vv * t1.x; R[5]  += vv * t1.y; R[6]  += vv * t1.z; R[7]  += vv * t1.w;
    R[8]  += vv * t2.x; R[9]  += vv * t2.y; R[10] += vv * t2.z; R[11] += vv * t2.w;
    R[12] += vv * t3.x; R[13] += vv * t3.y; R[14] += vv * t3.z; R[15] += vv * t3.w;
}

// sparse row gather: unrolled x4 with front-batched loads
__device__ __forceinline__ void spmm_row(const float* sBuf, size_t ebase, int cnt,
                                         int tid, float R[16])
{
    #pragma unroll
    for (int j = 0; j < 16; j++) R[j] = 0.f;
    size_t idx = ebase + tid;
    int e = 0;
    for (; e + 4 <= cnt; e += 4) {
        float2 p0 = g_ell[idx];
        float2 p1 = g_ell[idx + Nn];
        float2 p2 = g_ell[idx + 2 * Nn];
        float2 p3 = g_ell[idx + 3 * Nn];
        idx += 4 * Nn;
        ell_acc(sBuf, p0, R);
        ell_acc(sBuf, p1, R);
        ell_acc(sBuf, p2, R);
        ell_acc(sBuf, p3, R);
    }
    for (; e < cnt; e++) {
        float2 p = g_ell[idx];
        idx += Nn;
        ell_acc(sBuf, p, R);
    }
}

__global__ __launch_bounds__(256, 3)
void k_fgw(const float* __restrict__ x,
           const float* __restrict__ tA,
           const float* __restrict__ tF,
           const float* __restrict__ q0,
           const float* __restrict__ a0,
           float* __restrict__ out)
{
    // sT: features (2048) / dT staging (256*20=5120) / Kr transposed (16*321=5136)
    __shared__ __align__(16) float sT[5140];
    __shared__ __align__(16) float sU[Nn + Nn / 4];    // padded u buffer
    __shared__ __align__(16) float sW[Mm];             // scaled v (warm-started across CG)
    __shared__ __align__(16) float sPart[8 * 4];       // line-search warp partials
    __shared__ __align__(16) float sC2[Mm * Mm];
    __shared__ int   sChgP[2];                         // parity convergence flags
    __shared__ int   sBid;                             // grabbed problem id
    __shared__ float scc2[Mm];
    __shared__ float sCq[Mm];                          // (C2 @ q)_j
    __shared__ float sq256[Mm];                        // 256 * q_j
    __shared__ float sq[Mm];
    __shared__ float sFn[Mm];
    __shared__ float sred[16];

    const int tid  = threadIdx.x;
    const int lane = tid & 31;
    const int wid  = tid >> 5;
    const float L2E = 1.44269504088896340736f;

    const float alpha = 1.f / (1.f + expf(-a0[0]));

    const int rb   = lane & 15;               // col thread: owns rows [16rb, 16rb+16)
    const int jcol = 2 * wid + (lane >> 4);   // col thread: owned column

    for (;;) {
        // ===== grab next problem =====
        if (tid == 0) sBid = atomicAdd(&g_work, 1);
        __syncthreads();                       // broadcast bid + fence smem reuse
        const int bid = sBid;
        if (bid >= PROB) break;
        const int b = bid >> 4;
        const int k = bid & 15;
        const size_t sbase = ((size_t)bid * Nn + tid) * Mm;
        const size_t ebase = (size_t)b * CAP * Nn;

        // --- load C2, q softmax, features ---
        sC2[tid] = tA[k * 256 + tid];
        if (tid == 0) {
            float qv[16], mq = -1e30f;
            #pragma unroll
            for (int j = 0; j < 16; j++) { qv[j] = q0[k * 16 + j]; mq = fmaxf(mq, qv[j]); }
            float s = 0.f;
            #pragma unroll
            for (int j = 0; j < 16; j++) { qv[j] = ex2((qv[j] - mq) * L2E); s += qv[j]; }
            float inv = 1.f / s;
            #pragma unroll
            for (int j = 0; j < 16; j++) {
                float qq = qv[j] * inv;
                sq[j] = qq;
                sq256[j] = 256.f * qq;
            }
        }
        for (int t = tid; t < Mm * Dd; t += 256) sT[t] = tF[k * Mm * Dd + t];
        __syncthreads();

        if (tid < 16) {
            float s = 0.f, cq = 0.f;
            #pragma unroll
            for (int l = 0; l < 16; l++) {
                float c = sC2[tid * 16 + l];
                s  += c * c * sq[l];
                cq += c * sq[l];
            }
            scc2[tid] = s;
            sCq[tid]  = cq;
            float fn = 0.f;
            for (int d = 0; d < Dd; d++) { float f = sT[tid * Dd + d]; fn += f * f; }
            sFn[tid] = fn;
            sW[tid] = 1.f;   // Sinkhorn scaling init per problem; warm across CG
        }

        // leader-lane persistent registers (per problem)
        float Wo = 1.f;
        float q256j = sq256[jcol];

        const int grow = b * Nn + tid;
        const int cnt = g_cnt[grow];
        const float cc1 = g_cc1[grow];
        const float rs  = g_rs[grow];

        // --- Mcost row -> g_Mr ---
        {
            float Mr[16];
            #pragma unroll
            for (int j = 0; j < 16; j++) Mr[j] = 0.f;
            float xn = 0.f;
            const float4* xr = (const float4*)(x + ((size_t)(b * Nn + tid)) * Dd);
            for (int d4 = 0; d4 < Dd / 4; d4++) {
                float4 xv = xr[d4];
                xn += xv.x * xv.x + xv.y * xv.y + xv.z * xv.z + xv.w * xv.w;
                #pragma unroll
                for (int j = 0; j < 16; j++) {
                    float4 fv = ((const float4*)sT)[j * (Dd / 4) + d4];
                    Mr[j] += xv.x * fv.x + xv.y * fv.y + xv.z * fv.z + xv.w * fv.w;
                }
            }
            __syncthreads();   // sFn/sCq ready; feature reads done
            float4* mp = (float4*)(g_Mr + sbase);
            #pragma unroll
            for (int j4 = 0; j4 < 4; j4++) {
                float4 v;
                v.x = xn + sFn[j4 * 4 + 0] - 2.f * Mr[j4 * 4 + 0];
                v.y = xn + sFn[j4 * 4 + 1] - 2.f * Mr[j4 * 4 + 1];
                v.z = xn + sFn[j4 * 4 + 2] - 2.f * Mr[j4 * 4 + 2];
                v.w = xn + sFn[j4 * 4 + 3] - 2.f * Mr[j4 * 4 + 3];
                mp[j4] = v;
            }
            // ===== rank-1 prologue: CTC0[i][j] = rs_i * (C2 q)_j -> g_CT =====
            float4* cp = (float4*)(g_CT + sbase);
            #pragma unroll
            for (int j4 = 0; j4 < 4; j4++)
                cp[j4] = make_float4(rs * sCq[j4 * 4 + 0], rs * sCq[j4 * 4 + 1],
                                     rs * sCq[j4 * 4 + 2], rs * sCq[j4 * 4 + 3]);
        }

        float T[16];
        #pragma unroll
        for (int j = 0; j < 16; j++) T[j] = sq[j] * (1.f / Nn);

        for (int it = 0; it < CG_ITERS; it++) {
            // ===== B: gradient -> Kr, block max|grad| =====
            float Kr[16];
            float mxa = 0.f;
            {
                const float4* mp4 = (const float4*)(g_Mr + sbase);
                const float4* cp4 = (const float4*)(g_CT + sbase);
                #pragma unroll
                for (int j4 = 0; j4 < 4; j4++) {
                    float4 mv = mp4[j4];
                    float4 cv = cp4[j4];
                    float g0 = (1.f - alpha) * mv.x + 2.f * alpha * (cc1 + scc2[j4*4+0] - 2.f * cv.x);
                    float g1 = (1.f - alpha) * mv.y + 2.f * alpha * (cc1 + scc2[j4*4+1] - 2.f * cv.y);
                    float g2 = (1.f - alpha) * mv.z + 2.f * alpha * (cc1 + scc2[j4*4+2] - 2.f * cv.z);
                    float g3 = (1.f - alpha) * mv.w + 2.f * alpha * (cc1 + scc2[j4*4+3] - 2.f * cv.w);
                    Kr[j4*4+0] = g0; Kr[j4*4+1] = g1; Kr[j4*4+2] = g2; Kr[j4*4+3] = g3;
                    mxa = fmaxf(mxa, fmaxf(fmaxf(fabsf(g0), fabsf(g1)), fmaxf(fabsf(g2), fabsf(g3))));
                }
            }
            #pragma unroll
            for (int o = 16; o; o >>= 1) mxa = fmaxf(mxa, __shfl_xor_sync(0xffffffffu, mxa, o));
            if (lane == 0) sred[wid] = mxa;
            __syncthreads();
            {
                float m = fmaxf(fmaxf(fmaxf(sred[0], sred[1]), fmaxf(sred[2], sred[3])),
                                fmaxf(fmaxf(sred[4], sred[5]), fmaxf(sred[6], sred[7])));
                float cscale = -L2E / (0.01f * m + 1e-12f);
                float rmax = -1e30f;
                #pragma unroll
                for (int j = 0; j < 16; j++) { Kr[j] *= cscale; rmax = fmaxf(rmax, Kr[j]); }
                #pragma unroll
                for (int j = 0; j < 16; j++) Kr[j] = ex2(Kr[j] - rmax);   // (0,1]
            }
            __syncthreads();   // sred read done; sT free

            // ===== C: stage Kr transposed, read own column slice =====
            #pragma unroll
            for (int j = 0; j < 16; j++)
                sT[j * STRC + tid] = Kr[j];
            if (tid == 0) { sChgP[0] = 0; sChgP[1] = 0; }
            __syncthreads();
            float Kc_t[16];
            #pragma unroll
            for (int r = 0; r < 16; r++)
                Kc_t[r] = sT[jcol * STRC + 16 * rb + r];

            // ===== D: Sinkhorn, warm-started W, SOR, parity flags =====
            float U = 0.f;
            for (int sk = 0; sk < SINK_ITERS; sk++) {
                int p = sk & 1;
                {
                    const float4* wp = (const float4*)sW;
                    float4 w0 = wp[0], w1 = wp[1], w2 = wp[2], w3 = wp[3];
                    float s0 = Kr[0]  * w0.x + Kr[1]  * w0.y + Kr[2]  * w0.z + Kr[3]  * w0.w;
                    float s1 = Kr[4]  * w1.x + Kr[5]  * w1.y + Kr[6]  * w1.z + Kr[7]  * w1.w;
                    float s2 = Kr[8]  * w2.x + Kr[9]  * w2.y + Kr[10] * w2.z + Kr[11] * w2.w;
                    float s3 = Kr[12] * w3.x + Kr[13] * w3.y + Kr[14] * w3.z + Kr[15] * w3.w;
                    float s = fmaxf((s0 + s1) + (s2 + s3), 1e-30f);
                    U = rcpa(s);
                    sU[FPAD(tid)] = U;
                }
                __syncthreads();
                {
                    const float4* up = (const float4*)(sU + rb * STR);
                    float4 a = up[0], bb = up[1], c = up[2], d = up[3];
                    float part = Kc_t[0]  * a.x  + Kc_t[1]  * a.y  + Kc_t[2]  * a.z  + Kc_t[3]  * a.w
                               + Kc_t[4]  * bb.x + Kc_t[5]  * bb.y + Kc_t[6]  * bb.z + Kc_t[7]  * bb.w
                               + Kc_t[8]  * c.x  + Kc_t[9]  * c.y  + Kc_t[10] * c.z  + Kc_t[11] * c.w
                               + Kc_t[12] * d.x  + Kc_t[13] * d.y  + Kc_t[14] * d.z  + Kc_t[15] * d.w;
                    part += __shfl_xor_sync(0xffffffffu, part, 1);
                    part += __shfl_xor_sync(0xffffffffu, part, 2);
                    part += __shfl_xor_sync(0xffffffffu, part, 4);
                    part += __shfl_xor_sync(0xffffffffu, part, 8);
                    if (rb == 0) {
                        float Wn = q256j * rcpa(fmaxf(part, 1e-30f));
                        bool chg = fabsf(Wn - Wo) > 1e-4f * Wo;
                        float Wr = Wn;
                        if (chg && sk > 0)
                            Wr = Wn * ex2(0.4f * lg2(Wn * rcpa(Wo)));
                        sW[jcol] = Wr;
                        Wo = Wr;
                        if (chg) sChgP[p] = 1;
                    }
                    if (tid == 0) sChgP[p ^ 1] = 0;
                }
                __syncthreads();
                if (sChgP[p] == 0) break;
            }

            // ===== E+F: dT, stage dT, exit partials -> ONE barrier =====
            float dT[16];
            float mdt = 0.f, mT = 0.f;
            {
                const float4* wp = (const float4*)sW;
                float4 w0 = wp[0], w1 = wp[1], w2 = wp[2], w3 = wp[3];
                float Wv[16] = { w0.x,w0.y,w0.z,w0.w, w1.x,w1.y,w1.z,w1.w,
                                 w2.x,w2.y,w2.z,w2.w, w3.x,w3.y,w3.z,w3.w };
                float Us = U * (1.f / 256.f);
                #pragma unroll
                for (int j = 0; j < 16; j++) {
                    dT[j] = Us * Kr[j] * Wv[j] - T[j];
                    mdt = fmaxf(mdt, fabsf(dT[j]));
                    mT  = fmaxf(mT, T[j]);
                }
            }
            {
                float4* st = (float4*)(sT + tid * STR);
                st[0] = make_float4(dT[0], dT[1], dT[2], dT[3]);
                st[1] = make_float4(dT[4], dT[5], dT[6], dT[7]);
                st[2] = make_float4(dT[8], dT[9], dT[10], dT[11]);
                st[3] = make_float4(dT[12], dT[13], dT[14], dT[15]);
            }
            #pragma unroll
            for (int o = 16; o; o >>= 1) {
                mdt = fmaxf(mdt, __shfl_xor_sync(0xffffffffu, mdt, o));
                mT  = fmaxf(mT,  __shfl_xor_sync(0xffffffffu, mT,  o));
            }
            if (lane == 0) { sred[wid] = mdt; sred[8 + wid] = mT; }
            __syncthreads();   // staging + partials visible
            {
                float Mdt = fmaxf(fmaxf(fmaxf(sred[0], sred[1]), fmaxf(sred[2], sred[3])),
                                  fmaxf(fmaxf(sred[4], sred[5]), fmaxf(sred[6], sred[7])));
                float MT  = fmaxf(fmaxf(fmaxf(sred[8], sred[9]), fmaxf(sred[10], sred[11])),
                                  fmaxf(fmaxf(sred[12], sred[13]), fmaxf(sred[14], sred[15])));
                // plan step negligible: remaining CG iterations change T by <= ~1e-5
                // relative; T and g_CT stay exactly consistent (nothing applied).
                if (Mdt <= 1e-5f * MT) break;
            }

            // ===== F: D = C1 @ dT @ C2^T (dT already staged) =====
            float Rd[16];
            spmm_row(sT, ebase, cnt, tid, Rd);
            float D[16];
            #pragma unroll
            for (int jj = 0; jj < 16; jj++) {
                float s = 0.f;
                #pragma unroll
                for (int l4 = 0; l4 < 4; l4++) {
                    float4 c4 = ((const float4*)sC2)[jj * 4 + l4];
                    s += Rd[l4 * 4 + 0] * c4.x + Rd[l4 * 4 + 1] * c4.y
                       + Rd[l4 * 4 + 2] * c4.z + Rd[l4 * 4 + 3] * c4.w;
                }
                D[jj] = s;
            }

            // ===== G: line search (3 reductions, ONE barrier, redundant finish) =====
            float pa = 0.f, pb1 = 0.f, pb23 = 0.f;
            {
                const float4* mp4 = (const float4*)(g_Mr + sbase);
                const float4* cp4 = (const float4*)(g_CT + sbase);
                #pragma unroll
                for (int j4 = 0; j4 < 4; j4++) {
                    float4 mv = mp4[j4];
                    float4 cv = cp4[j4];
                    pa  += D[j4*4+0] * dT[j4*4+0] + D[j4*4+1] * dT[j4*4+1]
                         + D[j4*4+2] * dT[j4*4+2] + D[j4*4+3] * dT[j4*4+3];
                    pb1 += mv.x * dT[j4*4+0] + mv.y * dT[j4*4+1]
                         + mv.z * dT[j4*4+2] + mv.w * dT[j4*4+3];
                    pb23 += D[j4*4+0] * T[j4*4+0] + D[j4*4+1] * T[j4*4+1]
                          + D[j4*4+2] * T[j4*4+2] + D[j4*4+3] * T[j4*4+3]
                          + cv.x * dT[j4*4+0] + cv.y * dT[j4*4+1]
                          + cv.z * dT[j4*4+2] + cv.w * dT[j4*4+3];
                }
            }
            #pragma unroll
            for (int o = 16; o; o >>= 1) {
                pa   += __shfl_xor_sync(0xffffffffu, pa, o);
                pb1  += __shfl_xor_sync(0xffffffffu, pb1, o);
                pb23 += __shfl_xor_sync(0xffffffffu, pb23, o);
            }
            if (lane == 0) {
                sPart[wid * 4 + 0] = pa;
                sPart[wid * 4 + 1] = pb1;
                sPart[wid * 4 + 2] = pb23;
            }
            __syncthreads();
            float ts;
            {
                float Sa = 0.f, S1 = 0.f, S23 = 0.f;
                #pragma unroll
                for (int w = 0; w < 8; w++) {
                    float4 pv = ((const float4*)sPart)[w];
                    Sa += pv.x; S1 += pv.y; S23 += pv.z;
                }
                float A  = -2.f * alpha * Sa;
                float Bc = (1.f - alpha) * S1 - 2.f * alpha * S23;
                if (A > 0.f) {
                    ts = -Bc / (2.f * A + 1e-16f);
                    ts = fminf(1.f, fmaxf(0.f, ts));
                } else {
                    ts = (A + Bc < 0.f) ? 1.f : 0.f;
                }
            }
            if (ts == 0.f) break;     // uniform: exact no-op for remaining CG iters
            #pragma unroll
            for (int j = 0; j < 16; j++) T[j] += ts * dT[j];
            {
                float4* cp = (float4*)(g_CT + sbase);
                #pragma unroll
                for (int j4 = 0; j4 < 4; j4++) {
                    float4 cv = cp[j4];
                    cv.x += ts * D[j4*4+0]; cv.y += ts * D[j4*4+1];
                    cv.z += ts * D[j4*4+2]; cv.w += ts * D[j4*4+3];
                    cp[j4] = cv;
                }
            }
        }

        // ===== epilogue (CTC from g_CT matches final T) =====
        float pg = 0.f, pl = 0.f;
        {
            const float4* mp4 = (const float4*)(g_Mr + sbase);
            const float4* cp4 = (const float4*)(g_CT + sbase);
            #pragma unroll
            for (int j4 = 0; j4 < 4; j4++) {
                float4 mv = mp4[j4];
                float4 cv = cp4[j4];
                pg += (cc1 + scc2[j4*4+0] - 2.f * cv.x) * T[j4*4+0]
                    + (cc1 + scc2[j4*4+1] - 2.f * cv.y) * T[j4*4+1]
                    + (cc1 + scc2[j4*4+2] - 2.f * cv.z) * T[j4*4+2]
                    + (cc1 + scc2[j4*4+3] - 2.f * cv.w) * T[j4*4+3];
                pl += mv.x * T[j4*4+0] + mv.y * T[j4*4+1]
                    + mv.z * T[j4*4+2] + mv.w * T[j4*4+3];
            }
        }
        #pragma unroll
        for (int o = 16; o; o >>= 1) {
            pg += __shfl_xor_sync(0xffffffffu, pg, o);
            pl += __shfl_xor_sync(0xffffffffu, pl, o);
        }
        if (lane == 0) { sPart[wid * 2] = pg; sPart[wid * 2 + 1] = pl; }
        __syncthreads();
        if (tid == 0) {
            float Gw = 0.f, L = 0.f;
            #pragma unroll
            for (int w = 0; w < 8; w++) { Gw += sPart[w * 2]; L += sPart[w * 2 + 1]; }
            out[bid] = (1.f - alpha) * L + alpha * Gw;
        }
        // next loop iteration starts with a barrier (bid broadcast) which also
        // fences all smem reuse across problems
    }
}

// ============================ launch ============================

extern "C" void kernel_launch(void* const* d_in, const int* in_sizes, int n_in,
                              void* d_out, int out_size)
{
    const float* x  = (const float*)d_in[0];
    const int*   ei = (const int*)  d_in[1];
    const float* tA = (const float*)d_in[3];
    const float* tF = (const float*)d_in[4];
    const float* q0 = (const float*)d_in[5];
    const float* a0 = (const float*)d_in[6];
    int E = in_sizes[1] / 2;

    k_zero<<<8192, 256>>>();
    k_scatter<<<(E + 255) / 256, 256>>>(ei, E);
    k_csr<<<(Bg * Nn * 32 + 255) / 256, 256>>>();
    k_fgw<<<NCTA, 256>>>(x, tA, tF, q0, a0, (float*)d_out);
}